// round 1
// baseline (speedup 1.0000x reference)
#include <cuda_runtime.h>

#define Bz  8
#define Nn  8192
#define Dm  256
#define Hh  4
#define Rr  64
#define HDd 64
#define Mm  (Bz*Nn)          // 65536 rows
#define NITER 8              // row-tiles (64 rows) per kattn block

// ---------- scratch (device globals: allocation-free) ----------
__device__ float g_WK[Dm*Dm];                 // folded Wq @ K^T / 8
__device__ float g_bK[Dm];                    // folded bias
__device__ float g_xv[(size_t)Mm*Dm];         // x @ Wv + bv           (64 MB)
__device__ float g_e [(size_t)Mm*Dm];         // exp(attn)             (64 MB)
__device__ float g_pool[Bz*Hh*Rr*HDd];        // pooled (later *1/S)   (512 KB)
__device__ float g_S [Bz*Hh*Rr];              // sum_n e

// ---------- zero accumulators ----------
__global__ void kzero() {
    int i = blockIdx.x*blockDim.x + threadIdx.x;
    if (i < Bz*Hh*Rr*HDd) g_pool[i] = 0.f;
    if (i < Bz*Hh*Rr)     g_S[i]   = 0.f;
}

// ---------- fold Wq and K into WK (and bq into bK) ----------
__global__ void kprep(const float* __restrict__ Wq, const float* __restrict__ bq,
                      const float* __restrict__ K) {
    int col = threadIdx.x;                // 0..255  = h*64 + r
    int h = col >> 6, r = col & 63;
    const float* Krow = K + r*Dm + h*HDd; // K[(r*H + h)*64 + d]
    if (blockIdx.x < Dm) {
        int c = blockIdx.x;
        const float* wq = Wq + c*Dm + h*HDd;
        float s = 0.f;
        #pragma unroll 16
        for (int d = 0; d < HDd; d++) s = fmaf(wq[d], Krow[d], s);
        g_WK[c*Dm + col] = 0.125f * s;
    } else {
        float s = 0.f;
        #pragma unroll 16
        for (int d = 0; d < HDd; d++) s = fmaf(bq[h*HDd + d], Krow[d], s);
        g_bK[col] = 0.125f * s;
    }
}

// ---------- xv = x @ Wv + bv  (64x64 tile SGEMM, 4x4/thread) ----------
__global__ void kgemm_xv(const float* __restrict__ A, const float* __restrict__ W,
                         const float* __restrict__ bias) {
    __shared__ float As[16][68];   // [k][m] transposed
    __shared__ float Ws[16][68];   // [k][n]
    int t  = threadIdx.x;
    int m0 = blockIdx.x * 64, n0 = blockIdx.y * 64;
    int ty = t >> 4, tx = t & 15;
    int lrow = t >> 2, lkq = t & 3;     // A loader
    int lkk  = t >> 4, lj4 = t & 15;    // W loader
    float acc[4][4] = {};
    for (int k0 = 0; k0 < Dm; k0 += 16) {
        float4 av = *(const float4*)(A + (size_t)(m0 + lrow)*Dm + k0 + lkq*4);
        float4 wv = *(const float4*)(W + (size_t)(k0 + lkk)*Dm + n0 + lj4*4);
        __syncthreads();
        As[lkq*4+0][lrow] = av.x; As[lkq*4+1][lrow] = av.y;
        As[lkq*4+2][lrow] = av.z; As[lkq*4+3][lrow] = av.w;
        *(float4*)&Ws[lkk][lj4*4] = wv;
        __syncthreads();
        #pragma unroll
        for (int kk = 0; kk < 16; kk++) {
            float4 a = *(const float4*)&As[kk][ty*4];
            float4 b = *(const float4*)&Ws[kk][tx*4];
            float ar[4] = {a.x, a.y, a.z, a.w};
            float br[4] = {b.x, b.y, b.z, b.w};
            #pragma unroll
            for (int i = 0; i < 4; i++)
                #pragma unroll
                for (int j = 0; j < 4; j++)
                    acc[i][j] = fmaf(ar[i], br[j], acc[i][j]);
        }
    }
    float4 bb = *(const float4*)(bias + n0 + tx*4);
    #pragma unroll
    for (int i = 0; i < 4; i++) {
        float4 o = {acc[i][0]+bb.x, acc[i][1]+bb.y, acc[i][2]+bb.z, acc[i][3]+bb.w};
        *(float4*)(g_xv + (size_t)(m0 + ty*4 + i)*Dm + n0 + tx*4) = o;
    }
}

// ---------- attn GEMM + exp + r-softmax + pooled accumulation ----------
__global__ void kattn(const float* __restrict__ Z) {
    __shared__ float Zs[16][68];
    __shared__ float Ws[16][68];
    __shared__ float Es[64][68];   // e values, then A1 (normalized)
    __shared__ float XVs[64][68];  // xv head slice
    int t = threadIdx.x;
    int h = blockIdx.y;
    int m_base = blockIdx.x * (64*NITER);
    int b = m_base / Nn;
    int ty = t >> 4, tx = t & 15;
    int lrow = t >> 2, lkq = t & 3;
    int lkk  = t >> 4, lj4 = t & 15;
    int srow = t >> 2, srq = t & 3;   // softmax mapping
    float pool[4][4] = {};
    float4 bk = *(const float4*)(g_bK + h*64 + tx*4);

    for (int it = 0; it < NITER; it++) {
        int m0 = m_base + it*64;
        float acc[4][4] = {};
        for (int k0 = 0; k0 < Dm; k0 += 16) {
            float4 av = *(const float4*)(Z + (size_t)(m0 + lrow)*Dm + k0 + lkq*4);
            float4 wv = *(const float4*)(g_WK + (size_t)(k0 + lkk)*Dm + h*64 + lj4*4);
            __syncthreads();
            Zs[lkq*4+0][lrow] = av.x; Zs[lkq*4+1][lrow] = av.y;
            Zs[lkq*4+2][lrow] = av.z; Zs[lkq*4+3][lrow] = av.w;
            *(float4*)&Ws[lkk][lj4*4] = wv;
            __syncthreads();
            #pragma unroll
            for (int kk = 0; kk < 16; kk++) {
                float4 a = *(const float4*)&Zs[kk][ty*4];
                float4 bq4 = *(const float4*)&Ws[kk][tx*4];
                float ar[4] = {a.x, a.y, a.z, a.w};
                float br[4] = {bq4.x, bq4.y, bq4.z, bq4.w};
                #pragma unroll
                for (int i = 0; i < 4; i++)
                    #pragma unroll
                    for (int j = 0; j < 4; j++)
                        acc[i][j] = fmaf(ar[i], br[j], acc[i][j]);
            }
        }
        // bias + exp; stage e to smem, stream e to global
        #pragma unroll
        for (int i = 0; i < 4; i++) {
            float4 e4;
            e4.x = __expf(acc[i][0] + bk.x);
            e4.y = __expf(acc[i][1] + bk.y);
            e4.z = __expf(acc[i][2] + bk.z);
            e4.w = __expf(acc[i][3] + bk.w);
            *(float4*)&Es[ty*4 + i][tx*4] = e4;
            *(float4*)(g_e + (size_t)(m0 + ty*4 + i)*Dm + h*64 + tx*4) = e4;
        }
        // load xv head slice for this tile
        #pragma unroll
        for (int p = 0; p < 4; p++) {
            int idx = t + p*256;
            int row = idx >> 4, d4 = idx & 15;
            *(float4*)&XVs[row][d4*4] =
                *(const float4*)(g_xv + (size_t)(m0 + row)*Dm + h*64 + d4*4);
        }
        __syncthreads();
        // r-softmax: 4 lanes/row (same warp), sum 16 each, shfl-combine, normalize
        {
            float s = 0.f;
            #pragma unroll 16
            for (int k = 0; k < 16; k++) s += Es[srow][srq*16 + k];
            s += __shfl_xor_sync(0xffffffffu, s, 1);
            s += __shfl_xor_sync(0xffffffffu, s, 2);
            float inv = 1.f / s;
            #pragma unroll 16
            for (int k = 0; k < 16; k++) Es[srow][srq*16 + k] *= inv;
        }
        __syncthreads();
        // pooled[r][d] += A1[n][r] * xv[n][d]
        #pragma unroll 4
        for (int n = 0; n < 64; n++) {
            float4 a  = *(const float4*)&Es[n][ty*4];
            float4 x4 = *(const float4*)&XVs[n][tx*4];
            float ar[4] = {a.x, a.y, a.z, a.w};
            float xr[4] = {x4.x, x4.y, x4.z, x4.w};
            #pragma unroll
            for (int i = 0; i < 4; i++)
                #pragma unroll
                for (int j = 0; j < 4; j++)
                    pool[i][j] = fmaf(ar[i], xr[j], pool[i][j]);
        }
        __syncthreads();
    }
    #pragma unroll
    for (int i = 0; i < 4; i++)
        #pragma unroll
        for (int j = 0; j < 4; j++)
            atomicAdd(&g_pool[((b*Hh + h)*Rr + ty*4 + i)*HDd + tx*4 + j], pool[i][j]);
}

// ---------- S[b,h,r] = sum_n e  (pure sum; chunked over n) ----------
#define NCH 16
__global__ void ksum() {
    int bid = blockIdx.x;
    int ch = bid & (NCH-1); int bh = bid / NCH;
    int h = bh & 3, b = bh >> 2;
    int t = threadIdx.x; int r = t & 63; int sub = t >> 6;
    int nbase = ch*(Nn/NCH) + sub*(Nn/NCH/4);
    const float* p = g_e + ((size_t)(b*Nn + nbase))*Dm + h*64 + r;
    float s = 0.f;
    #pragma unroll 8
    for (int k = 0; k < Nn/NCH/4; k++) s += p[(size_t)k*Dm];
    __shared__ float sh[256];
    sh[t] = s; __syncthreads();
    if (t < 64)
        atomicAdd(&g_S[(b*Hh + h)*64 + r], sh[t] + sh[t+64] + sh[t+128] + sh[t+192]);
}

// ---------- pooled *= 1/S ----------
__global__ void kfin() {
    int i = blockIdx.x*256 + threadIdx.x;     // 0..2047 = (b,h,r)
    float inv = 1.f / g_S[i];
    float4* p = (float4*)(g_pool + (size_t)i*HDd);
    #pragma unroll
    for (int d4 = 0; d4 < 16; d4++) {
        float4 v = p[d4];
        v.x *= inv; v.y *= inv; v.z *= inv; v.w *= inv;
        p[d4] = v;
    }
}

// ---------- redistribute + gated output ----------
#define STR 260
#define SMEM_OUT ((2*64*STR + Hh*Rr*HDd)*4)
__global__ void kout(const float* __restrict__ alpha, const float* __restrict__ beta,
                     float* __restrict__ out) {
    extern __shared__ float sm[];
    float* Es  = sm;                // 64 x 260
    float* XVs = sm + 64*STR;       // 64 x 260
    float* P2  = sm + 2*64*STR;     // [h][r][d] = 16384
    int t = threadIdx.x;
    int tile = blockIdx.x;
    int b = tile / (Nn/64);
    int n0 = (tile % (Nn/64)) * 64;
    size_t base = ((size_t)b*Nn + n0) * Dm;
    #pragma unroll
    for (int p = 0; p < 16; p++) {
        int idx = t + p*256;
        int row = idx >> 6, c4 = idx & 63;
        *(float4*)&Es [row*STR + c4*4] = *(const float4*)(g_e  + base + (size_t)row*Dm + c4*4);
        *(float4*)&XVs[row*STR + c4*4] = *(const float4*)(g_xv + base + (size_t)row*Dm + c4*4);
    }
    #pragma unroll
    for (int p = 0; p < 16; p++) {
        int idx = t + p*256;
        *(float4*)&P2[idx*4] = *(const float4*)(g_pool + (size_t)b*(Hh*Rr*HDd) + idx*4);
    }
    __syncthreads();
    int n = t & 63, h = t >> 6;
    float acc[64] = {};
    const float* Erow = Es + n*STR + h*64;
    const float* Ph = P2 + h*Rr*HDd;
    for (int r = 0; r < Rr; r++) {
        float e = Erow[r];
        const float4* pr = (const float4*)(Ph + r*HDd);
        #pragma unroll
        for (int d4 = 0; d4 < 16; d4++) {
            float4 pv = pr[d4];
            acc[d4*4+0] = fmaf(e, pv.x, acc[d4*4+0]);
            acc[d4*4+1] = fmaf(e, pv.y, acc[d4*4+1]);
            acc[d4*4+2] = fmaf(e, pv.z, acc[d4*4+2]);
            acc[d4*4+3] = fmaf(e, pv.w, acc[d4*4+3]);
        }
    }
    float sa = 1.f / (1.f + __expf(-alpha[h]));
    float sb = 1.f / (1.f + __expf(-beta[h]));
    float* op = out + base + (size_t)n*Dm + h*64;
    const float* xvp = XVs + n*STR + h*64;
    #pragma unroll
    for (int d4 = 0; d4 < 16; d4++) {
        float4 o;
        o.x = fmaf(sa, xvp[d4*4+0], sb*acc[d4*4+0]);
        o.y = fmaf(sa, xvp[d4*4+1], sb*acc[d4*4+1]);
        o.z = fmaf(sa, xvp[d4*4+2], sb*acc[d4*4+2]);
        o.w = fmaf(sa, xvp[d4*4+3], sb*acc[d4*4+3]);
        *(float4*)(op + d4*4) = o;
    }
}

extern "C" void kernel_launch(void* const* d_in, const int* in_sizes, int n_in,
                              void* d_out, int out_size) {
    const float* x     = (const float*)d_in[0];
    const float* z     = (const float*)d_in[1];
    const float* Wq    = (const float*)d_in[2];
    const float* bq    = (const float*)d_in[3];
    const float* K     = (const float*)d_in[4];
    const float* Wv    = (const float*)d_in[5];
    const float* bv    = (const float*)d_in[6];
    const float* alpha = (const float*)d_in[7];
    const float* beta  = (const float*)d_in[8];
    float* out = (float*)d_out;

    kzero<<<512, 256>>>();
    kprep<<<Dm + 1, 256>>>(Wq, bq, K);
    kgemm_xv<<<dim3(Mm/64, Dm/64), 256>>>(x, Wv, bv);
    kattn<<<dim3(Mm/(64*NITER), Hh), 256>>>(z);
    ksum<<<Bz*Hh*NCH, 256>>>();
    kfin<<<Bz*Hh*Rr/256, 256>>>();
    cudaFuncSetAttribute(kout, cudaFuncAttributeMaxDynamicSharedMemorySize, SMEM_OUT);
    kout<<<Mm/64, 256, SMEM_OUT>>>(alpha, beta, out);
}